// round 6
// baseline (speedup 1.0000x reference)
#include <cuda_runtime.h>
#include <cuda_bf16.h>
#include <stdint.h>

#define P_PTS   10000
#define NPTS    100
#define MAXB    4096
#define NITER   79          // ceil(10000/128)

typedef unsigned long long ull;

// ------------------------------ scratch ------------------------------------
__device__ float g_phiT[304 * MAXB];   // phi transposed [k][b]
__device__ float g_ht  [256 * MAXB];   // hidden transposed [k][b]
__device__ float g_W1t [304 * 128];    // W1 transposed [k][c]
__device__ float g_Wct [256 * 256];    // [W3|W4] transposed [k][j]
__device__ float g_b34 [256];          // b3 + b4

// ------------------------------ f32x2 helpers -------------------------------
union F4U2 { float4 f4; ull u2[2]; float f[4]; };

__device__ __forceinline__ ull dup2(float a) {
    ull r; asm("mov.b64 %0, {%1, %1};" : "=l"(r) : "f"(a)); return r;
}
__device__ __forceinline__ void ffma2(ull& acc, ull a, ull b) {
    asm("fma.rn.f32x2 %0, %1, %2, %3;" : "=l"(acc) : "l"(a), "l"(b), "l"(acc));
}
__device__ __forceinline__ float2 unpack2(ull v) {
    float2 f; asm("mov.b64 {%0, %1}, %2;" : "=f"(f.x), "=f"(f.y) : "l"(v)); return f;
}

// ------------------------------ foveate (+ folded prep) ---------------------
// Warp-per-batch: 8 warps/CTA, 128-pt chunks, ballot compaction, no CTA sync
// in the scan loop, depth-2 register prefetch. Writes g_phiT [k][b] coalesced.
__device__ __forceinline__ void ld_chunk(const float* xb, int it, int lane, float4* f) {
    int p0 = it * 128 + lane * 4;
    if (p0 < P_PTS) {
        f[0] = *(const float4*)(xb + p0);
        f[1] = *(const float4*)(xb + P_PTS + p0);
        f[2] = *(const float4*)(xb + 2 * P_PTS + p0);
    }
}

__global__ void __launch_bounds__(256) foveate_kernel(
        const float* __restrict__ x,  const float* __restrict__ lt,
        const float* __restrict__ W1, const float* __restrict__ W3,
        const float* __restrict__ W4, const float* __restrict__ b3,
        const float* __restrict__ b4) {
    __shared__ float s[8][3][NPTS];
    __shared__ int sn[8];
    int tid = threadIdx.x, lane = tid & 31, wid = tid >> 5;

    // folded prep (grid*block = 131072 threads covers 65536 elements)
    {
        int g = blockIdx.x * 256 + tid;
        if (g < 300 * 128) {
            int k = g / 128, c = g - k * 128;
            g_W1t[g] = W1[c * 300 + k];
        }
        if (g < 256 * 256) {
            int k = g >> 8, j = g & 255;
            g_Wct[g] = (k < 128) ? W3[j * 128 + k] : W4[j * 128 + (k - 128)];
        }
        if (g < 256) g_b34[g] = b3[g] + b4[g];
    }

    int b = blockIdx.x * 8 + wid;
    const float* xb = x + (size_t)b * (3 * P_PTS);
    float l0 = lt[b * 3 + 0], l1 = lt[b * 3 + 1], l2 = lt[b * 3 + 2];
    float lo0 = l0 - 0.25f, hi0 = l0 + 0.25f;
    float lo1 = l1 - 0.25f, hi1 = l1 + 0.25f;
    float lo2 = l2 - 0.25f, hi2 = l2 + 0.25f;
    unsigned ltm = (1u << lane) - 1u;

    float4 buf[2][3];
    ld_chunk(xb, 0, lane, buf[0]);
    ld_chunk(xb, 1, lane, buf[1]);

    int run = 0;
    for (int it = 0; it < NITER; it++) {
        float4 nf[3];
        bool have = (it + 2 < NITER);
        if (have) ld_chunk(xb, it + 2, lane, nf);

        float4* F = buf[it & 1];
        int p0 = it * 128 + lane * 4;
        float v0[4], v1[4], v2[4];
        unsigned m = 0;
        if (p0 < P_PTS) {
            v0[0]=F[0].x; v0[1]=F[0].y; v0[2]=F[0].z; v0[3]=F[0].w;
            v1[0]=F[1].x; v1[1]=F[1].y; v1[2]=F[1].z; v1[3]=F[1].w;
            v2[0]=F[2].x; v2[1]=F[2].y; v2[2]=F[2].z; v2[3]=F[2].w;
#pragma unroll
            for (int i = 0; i < 4; i++) {
                bool in = (v0[i] >= lo0) && (v0[i] <= hi0) &&
                          (v1[i] >= lo1) && (v1[i] <= hi1) &&
                          (v2[i] >= lo2) && (v2[i] <= hi2);
                m |= ((unsigned)in) << i;
            }
        }
        unsigned bl0 = __ballot_sync(0xffffffffu,  m       & 1u);
        unsigned bl1 = __ballot_sync(0xffffffffu, (m >> 1) & 1u);
        unsigned bl2 = __ballot_sync(0xffffffffu, (m >> 2) & 1u);
        unsigned bl3 = __ballot_sync(0xffffffffu, (m >> 3) & 1u);
        int tot = __popc(bl0) + __popc(bl1) + __popc(bl2) + __popc(bl3);
        int r = run + __popc(bl0 & ltm) + __popc(bl1 & ltm) +
                      __popc(bl2 & ltm) + __popc(bl3 & ltm);
#pragma unroll
        for (int i = 0; i < 4; i++) {
            if ((m >> i) & 1u) {
                if (r < NPTS) { s[wid][0][r] = v0[i]; s[wid][1][r] = v1[i]; s[wid][2][r] = v2[i]; }
                r++;
            }
        }
        run += tot;                 // warp-uniform
        if (have) { F[0] = nf[0]; F[1] = nf[1]; F[2] = nf[2]; }
        if (run >= NPTS) break;     // warp-uniform break
    }
    if (lane == 0) sn[wid] = run;
    __syncthreads();

    // write phi transposed: g_phiT[k][b], 8 batches per CTA -> 32B sectors
    for (int t = tid; t < 2400; t += 256) {
        int k = t >> 3, bb = t & 7;
        int n = sn[bb];
        int axis = k / 100, pos = k - axis * 100;
        float v = 0.0f;
        if (n > 0) {
            int j = (n >= NPTS) ? pos : (pos % n);
            v = s[bb][axis][j];
        }
        g_phiT[(size_t)k * MAXB + blockIdx.x * 8 + bb] = v;
    }
}

// ------------------------------ hidden layer --------------------------------
// h^T[:128] = relu(phi @ W1^T + b1): BM=16, BN=128, K=300, BK=20, 128 thr,
// thread tile 8 rows (4 f32x2 pairs, A broadcast) x 2 cols.
// h^T[128:] = relu(l @ W2^T + b2) direct. Writes g_ht transposed [k][b].
__global__ void __launch_bounds__(128) hidden_kernel(
        const float* __restrict__ lt, const float* __restrict__ b1,
        const float* __restrict__ W2, const float* __restrict__ b2) {
    __shared__ __align__(16) float As[300 * 16];
    __shared__ __align__(16) float Bs[2][20 * 128];
    __shared__ float T[128 * 17];
    __shared__ float ls[48];

    int row0 = blockIdx.x * 16;
    int tid = threadIdx.x, lane = tid & 31, wid = tid >> 5;
    int rbase = (wid >> 1) * 8;                 // 2 row groups of 8
    int c0 = ((wid & 1) * 32 + lane) * 2;       // 64 col groups of 2

    for (int idx = tid; idx < 1200; idx += 128) {
        int k = idx >> 2, rq = (idx & 3) * 4;
        *(float4*)&As[k * 16 + rq] = *(const float4*)&g_phiT[(size_t)k * MAXB + row0 + rq];
    }
    if (tid < 48) ls[tid] = lt[row0 * 3 + tid];
#pragma unroll
    for (int j = 0; j < 5; j++) {               // fill Bs[0] (tile 0)
        int idx = tid + j * 128;                // 640 float4 per tile
        int kk = idx >> 5, cq = (idx & 31) * 4;
        *(float4*)&Bs[0][kk * 128 + cq] = *(const float4*)&g_W1t[kk * 128 + cq];
    }

    ull acc[4][2];
#pragma unroll
    for (int p = 0; p < 4; p++) { acc[p][0] = dup2(b1[c0]); acc[p][1] = dup2(b1[c0 + 1]); }

    for (int kt = 0; kt < 15; kt++) {
        __syncthreads();
        float4 pw[5];
        if (kt + 1 < 15) {
            const float* src = g_W1t + (kt + 1) * 20 * 128;
#pragma unroll
            for (int j = 0; j < 5; j++) pw[j] = *(const float4*)(src + (tid + j * 128) * 4);
        }
        const float* Bc = Bs[kt & 1];
        int k0 = kt * 20;
#pragma unroll
        for (int kk = 0; kk < 20; kk++) {
            int k = k0 + kk;
            F4U2 a0, a1;
            a0.f4 = *(const float4*)&As[k * 16 + rbase];       // rows 0..3 (2 pairs)
            a1.f4 = *(const float4*)&As[k * 16 + rbase + 4];   // rows 4..7 (2 pairs)
            float2 w = *(const float2*)&Bc[kk * 128 + c0];
            ull d0 = dup2(w.x), d1 = dup2(w.y);
            ffma2(acc[0][0], a0.u2[0], d0); ffma2(acc[0][1], a0.u2[0], d1);
            ffma2(acc[1][0], a0.u2[1], d0); ffma2(acc[1][1], a0.u2[1], d1);
            ffma2(acc[2][0], a1.u2[0], d0); ffma2(acc[2][1], a1.u2[0], d1);
            ffma2(acc[3][0], a1.u2[1], d0); ffma2(acc[3][1], a1.u2[1], d1);
        }
        if (kt + 1 < 15) {
            float* dst = Bs[(kt + 1) & 1];
#pragma unroll
            for (int j = 0; j < 5; j++) *(float4*)(dst + (tid + j * 128) * 4) = pw[j];
        }
    }

    // stage transposed tile T[c][r] (stride 17, conflict-light), then coalesced store
#pragma unroll
    for (int c = 0; c < 2; c++) {
#pragma unroll
        for (int p = 0; p < 4; p++) {
            float2 v = unpack2(acc[p][c]);
            T[(c0 + c) * 17 + rbase + 2 * p    ] = fmaxf(v.x, 0.0f);
            T[(c0 + c) * 17 + rbase + 2 * p + 1] = fmaxf(v.y, 0.0f);
        }
    }
    __syncthreads();
    for (int idx = tid; idx < 2048; idx += 128) {
        int c = idx >> 4, r = idx & 15;
        g_ht[(size_t)c * MAXB + row0 + r] = T[c * 17 + r];
    }

    // l_out half: one col per thread, 16 contiguous rows in g_ht -> 4x STG.128
    {
        int c = tid;
        float w0 = W2[c * 3 + 0], w1 = W2[c * 3 + 1], w2 = W2[c * 3 + 2];
        float bc = b2[c];
        float v[16];
#pragma unroll
        for (int r = 0; r < 16; r++)
            v[r] = fmaxf(bc + ls[r * 3 + 0] * w0 + ls[r * 3 + 1] * w1 + ls[r * 3 + 2] * w2, 0.0f);
        float* dst = &g_ht[(size_t)(128 + c) * MAXB + row0];
#pragma unroll
        for (int q = 0; q < 4; q++)
            *(float4*)(dst + q * 4) = make_float4(v[q * 4], v[q * 4 + 1], v[q * 4 + 2], v[q * 4 + 3]);
    }
}

// ------------------------------ output layer --------------------------------
// out = relu(h @ Wc^T + b34): BM=32, BN=128, K=256, BK=16, 128 thr,
// thread tile 8 rows (pairs, A broadcast) x 4 cols. grid (B/32, 2).
__global__ void __launch_bounds__(128) out_kernel(float* __restrict__ out) {
    __shared__ __align__(16) float As[256 * 32];
    __shared__ __align__(16) float Bs[2][16 * 128];

    int row0 = blockIdx.x * 32, col0 = blockIdx.y * 128;
    int tid = threadIdx.x, lane = tid & 31, wid = tid >> 5;
    int rbase = wid * 8;        // 4 row groups of 8
    int c0 = lane * 4;          // 32 col groups of 4

    for (int idx = tid; idx < 2048; idx += 128) {
        int k = idx >> 3, rq = (idx & 7) * 4;
        *(float4*)&As[k * 32 + rq] = *(const float4*)&g_ht[(size_t)k * MAXB + row0 + rq];
    }
#pragma unroll
    for (int j = 0; j < 4; j++) {               // fill Bs[0] (tile 0), 512 float4
        int idx = tid + j * 128;
        int kk = idx >> 5, cq = (idx & 31) * 4;
        *(float4*)&Bs[0][kk * 128 + cq] = *(const float4*)&g_Wct[kk * 256 + col0 + cq];
    }

    ull acc[4][4];
#pragma unroll
    for (int p = 0; p < 4; p++)
#pragma unroll
        for (int c = 0; c < 4; c++) acc[p][c] = dup2(g_b34[col0 + c0 + c]);

    for (int kt = 0; kt < 16; kt++) {
        __syncthreads();
        float4 pw[4];
        if (kt + 1 < 16) {
            int kb = (kt + 1) * 16;
#pragma unroll
            for (int j = 0; j < 4; j++) {
                int idx = tid + j * 128;
                int kk = idx >> 5, cq = (idx & 31) * 4;
                pw[j] = *(const float4*)&g_Wct[(kb + kk) * 256 + col0 + cq];
            }
        }
        const float* Bc = Bs[kt & 1];
        int k0 = kt * 16;
#pragma unroll
        for (int kk = 0; kk < 16; kk++) {
            int k = k0 + kk;
            F4U2 a0, a1;
            a0.f4 = *(const float4*)&As[k * 32 + rbase];
            a1.f4 = *(const float4*)&As[k * 32 + rbase + 4];
            F4U2 w; w.f4 = *(const float4*)&Bc[kk * 128 + c0];
#pragma unroll
            for (int c = 0; c < 4; c++) {
                ull d = dup2(w.f[c]);
                ffma2(acc[0][c], a0.u2[0], d);
                ffma2(acc[1][c], a0.u2[1], d);
                ffma2(acc[2][c], a1.u2[0], d);
                ffma2(acc[3][c], a1.u2[1], d);
            }
        }
        if (kt + 1 < 16) {
            float* dst = Bs[(kt + 1) & 1];
#pragma unroll
            for (int j = 0; j < 4; j++) *(float4*)(dst + (tid + j * 128) * 4) = pw[j];
        }
    }

    __syncthreads();                 // done reading Bs -> reuse as staging
    float* T = (float*)Bs;           // 32 x 128 row-major
#pragma unroll
    for (int c = 0; c < 4; c++) {
#pragma unroll
        for (int p = 0; p < 4; p++) {
            float2 v = unpack2(acc[p][c]);
            T[(rbase + 2 * p    ) * 128 + c0 + c] = fmaxf(v.x, 0.0f);
            T[(rbase + 2 * p + 1) * 128 + c0 + c] = fmaxf(v.y, 0.0f);
        }
    }
    __syncthreads();
    for (int idx = tid; idx < 1024; idx += 128) {
        int r = idx >> 5, cq = (idx & 31) * 4;
        *(float4*)&out[(size_t)(row0 + r) * 256 + col0 + cq] = *(const float4*)&T[r * 128 + cq];
    }
}

// ------------------------------ launch --------------------------------------
extern "C" void kernel_launch(void* const* d_in, const int* in_sizes, int n_in,
                              void* d_out, int out_size) {
    const float* x  = (const float*)d_in[0];
    const float* lt = (const float*)d_in[1];
    const float* W1 = (const float*)d_in[2];
    const float* b1 = (const float*)d_in[3];
    const float* W2 = (const float*)d_in[4];
    const float* b2 = (const float*)d_in[5];
    const float* W3 = (const float*)d_in[6];
    const float* b3 = (const float*)d_in[7];
    const float* W4 = (const float*)d_in[8];
    const float* b4 = (const float*)d_in[9];
    float* out = (float*)d_out;

    int B = in_sizes[0] / (3 * P_PTS);
    if (B > MAXB) B = MAXB;

    foveate_kernel<<<B / 8, 256>>>(x, lt, W1, W3, W4, b3, b4);
    hidden_kernel<<<B / 16, 128>>>(lt, b1, W2, b2);
    out_kernel<<<dim3(B / 32, 2), 128>>>(out);
}

// round 7
// speedup vs baseline: 1.0360x; 1.0360x over previous
#include <cuda_runtime.h>
#include <cuda_bf16.h>
#include <stdint.h>

#define P_PTS   10000
#define NPTS    100
#define MAXB    4096

typedef unsigned long long ull;

// ------------------------------ scratch ------------------------------------
__device__ float g_phiT[304 * MAXB];   // phi transposed [k][b]
__device__ float g_W1t [304 * 128];    // W1 transposed [k][c]
__device__ float g_Wct [256 * 256];    // [W3|W4] transposed [k][j]
__device__ float g_b34 [256];          // b3 + b4

// ------------------------------ f32x2 helpers -------------------------------
union F4U2 { float4 f4; ull u2[2]; float f[4]; };

__device__ __forceinline__ ull dup2(float a) {
    ull r; asm("mov.b64 %0, {%1, %1};" : "=l"(r) : "f"(a)); return r;
}
__device__ __forceinline__ void ffma2(ull& acc, ull a, ull b) {
    asm("fma.rn.f32x2 %0, %1, %2, %3;" : "=l"(acc) : "l"(a), "l"(b), "l"(acc));
}
__device__ __forceinline__ float2 unpack2(ull v) {
    float2 f; asm("mov.b64 {%0, %1}, %2;" : "=f"(f.x), "=f"(f.y) : "l"(v)); return f;
}

// ------------------------------ foveate (+ folded prep) ---------------------
// CTA-per-batch, 512 threads, 512-pt chunks (1 scalar point per thread).
// Single ballot per warp, double-buffered warp counts, ONE sync per chunk,
// early exit at 100 collected points. Minimal overshoot (~1.1 chunks).
__global__ void __launch_bounds__(512) foveate_kernel(
        const float* __restrict__ x,  const float* __restrict__ lt,
        const float* __restrict__ W1, const float* __restrict__ W3,
        const float* __restrict__ W4, const float* __restrict__ b3,
        const float* __restrict__ b4) {
    __shared__ float s0[NPTS], s1[NPTS], s2[NPTS];
    __shared__ int warp_cnt[2][16];

    int b = blockIdx.x;
    int tid = threadIdx.x, lane = tid & 31, wid = tid >> 5;

    // ---- folded prep (independent; consumed by mlp kernel) ----
    {
        int g = b * 512 + tid;
        if (g < 300 * 128) {
            int k = g / 128, c = g - k * 128;
            g_W1t[g] = W1[c * 300 + k];
        }
        if (g < 256 * 256) {
            int k = g >> 8, j = g & 255;
            g_Wct[g] = (k < 128) ? W3[j * 128 + k] : W4[j * 128 + (k - 128)];
        }
        if (g < 256) g_b34[g] = b3[g] + b4[g];
    }

    const float* xb = x + (size_t)b * (3 * P_PTS);
    float l0 = lt[b * 3 + 0], l1 = lt[b * 3 + 1], l2 = lt[b * 3 + 2];
    float lo0 = l0 - 0.25f, hi0 = l0 + 0.25f;
    float lo1 = l1 - 0.25f, hi1 = l1 + 0.25f;
    float lo2 = l2 - 0.25f, hi2 = l2 + 0.25f;
    unsigned ltm = (1u << lane) - 1u;

    int run = 0, buf = 0;
    for (int base = 0; base < P_PTS; base += 512) {
        int p = base + tid;
        float v0 = 0.f, v1 = 0.f, v2 = 0.f;
        bool in = false;
        if (p < P_PTS) {
            v0 = xb[p];
            v1 = xb[P_PTS + p];
            v2 = xb[2 * P_PTS + p];
            in = (v0 >= lo0) && (v0 <= hi0) &&
                 (v1 >= lo1) && (v1 <= hi1) &&
                 (v2 >= lo2) && (v2 <= hi2);
        }
        unsigned bl = __ballot_sync(0xffffffffu, in);
        if (lane == 0) warp_cnt[buf][wid] = __popc(bl);
        int excl = __popc(bl & ltm);
        __syncthreads();

        int woff = 0, tot = 0;
#pragma unroll
        for (int w = 0; w < 16; w++) {
            int v = warp_cnt[buf][w];
            tot += v;
            if (w < wid) woff += v;
        }
        if (in) {
            int r = run + woff + excl;
            if (r < NPTS) { s0[r] = v0; s1[r] = v1; s2[r] = v2; }
        }
        run += tot;          // identical in every thread -> uniform break
        buf ^= 1;
        if (run >= NPTS) break;
    }
    __syncthreads();         // scatter visible to all

    int n = run;
    for (int t = tid; t < 300; t += 512) {
        int axis = t / 100, pos = t - axis * 100;
        float v = 0.0f;
        if (n > 0) {
            int j = (n >= NPTS) ? pos : (pos % n);
            v = (axis == 0) ? s0[j] : ((axis == 1) ? s1[j] : s2[j]);
        }
        g_phiT[(size_t)t * MAXB + b] = v;   // merged into sectors across CTAs
    }
}

// ------------------------------ fused MLP -----------------------------------
// Per CTA: 16 batch rows, 128 threads.
// Phase 1: hA[k][r] (k=0..255, transposed in smem) =
//          relu(phi @ W1^T + b1) for k<128, relu(l @ W2^T + b2) for k>=128.
// Phase 2: out[r][:] = relu(hA^T @ Wc^T + b34), Wct streamed double-buffered.
// Dynamic smem: pool (phase1 phiAs+W1 tiles, aliased by phase2 Wct tiles)
//               + hA (stride 20) + ls.
#define HA_STRIDE 20
#define POOL_FLOATS 9920          // 4800 (phiAs) + 2*2560 (W1 tiles) >= 2*4096 (Wct tiles)
#define SMEM_FLOATS (POOL_FLOATS + 256 * HA_STRIDE + 48)

extern __shared__ float sm_dyn[];

__global__ void __launch_bounds__(128) mlp_kernel(
        const float* __restrict__ lt, const float* __restrict__ b1,
        const float* __restrict__ W2, const float* __restrict__ b2,
        float* __restrict__ out) {
    float* pool  = sm_dyn;                    // phase1: phiAs | W1 tiles ; phase2: Wct tiles
    float* phiAs = pool;                      // [k*16 + r], k < 300
    float* w1Bs  = pool + 4800;               // [2][20*128]
    float* wctBs = pool;                      // [2][16*256] (alias, after sync)
    float* hA    = sm_dyn + POOL_FLOATS;      // [c * 20 + r]
    float* ls    = hA + 256 * HA_STRIDE;      // [48]

    int row0 = blockIdx.x * 16;
    int tid = threadIdx.x, lane = tid & 31, wid = tid >> 5;
    int rbase = (wid >> 1) * 8;               // row group: 0 or 8
    int cg = (wid & 1) * 32 + lane;           // col group 0..63

    // ---- phase 1 staging ----
    for (int idx = tid; idx < 1200; idx += 128) {
        int k = idx >> 2, rq = (idx & 3) * 4;
        *(float4*)&phiAs[k * 16 + rq] = *(const float4*)&g_phiT[(size_t)k * MAXB + row0 + rq];
    }
    if (tid < 48) ls[tid] = lt[row0 * 3 + tid];
#pragma unroll
    for (int j = 0; j < 5; j++) {             // W1 tile 0 (640 float4)
        int idx = tid + j * 128;
        int kk = idx >> 5, cq = (idx & 31) * 4;
        *(float4*)&w1Bs[kk * 128 + cq] = *(const float4*)&g_W1t[kk * 128 + cq];
    }

    int c0 = cg * 2;                          // phase-1 col pair
    ull acc[4][2];
#pragma unroll
    for (int p = 0; p < 4; p++) { acc[p][0] = dup2(b1[c0]); acc[p][1] = dup2(b1[c0 + 1]); }

    // ---- phase 1 mainloop: 15 K-tiles of 20 ----
    for (int kt = 0; kt < 15; kt++) {
        __syncthreads();
        float4 pw[5];
        if (kt + 1 < 15) {
            const float* src = g_W1t + (kt + 1) * 20 * 128;
#pragma unroll
            for (int j = 0; j < 5; j++) pw[j] = *(const float4*)(src + (tid + j * 128) * 4);
        }
        const float* Bc = w1Bs + (kt & 1) * 2560;
        int k0 = kt * 20;
#pragma unroll
        for (int kk = 0; kk < 20; kk++) {
            int k = k0 + kk;
            F4U2 a0, a1;
            a0.f4 = *(const float4*)&phiAs[k * 16 + rbase];
            a1.f4 = *(const float4*)&phiAs[k * 16 + rbase + 4];
            float2 w = *(const float2*)&Bc[kk * 128 + c0];
            ull d0 = dup2(w.x), d1 = dup2(w.y);
            ffma2(acc[0][0], a0.u2[0], d0); ffma2(acc[0][1], a0.u2[0], d1);
            ffma2(acc[1][0], a0.u2[1], d0); ffma2(acc[1][1], a0.u2[1], d1);
            ffma2(acc[2][0], a1.u2[0], d0); ffma2(acc[2][1], a1.u2[0], d1);
            ffma2(acc[3][0], a1.u2[1], d0); ffma2(acc[3][1], a1.u2[1], d1);
        }
        if (kt + 1 < 15) {
            float* dst = w1Bs + ((kt + 1) & 1) * 2560;
#pragma unroll
            for (int j = 0; j < 5; j++) *(float4*)(dst + (tid + j * 128) * 4) = pw[j];
        }
    }

    // ---- phase 1 epilogue: write transposed h into hA ----
#pragma unroll
    for (int c = 0; c < 2; c++) {
#pragma unroll
        for (int p = 0; p < 4; p++) {
            float2 v = unpack2(acc[p][c]);
            hA[(c0 + c) * HA_STRIDE + rbase + 2 * p    ] = fmaxf(v.x, 0.0f);
            hA[(c0 + c) * HA_STRIDE + rbase + 2 * p + 1] = fmaxf(v.y, 0.0f);
        }
    }
    // l_out: one column per thread (cols 128..255), 16 rows
    {
        int c = tid;
        float w0 = W2[c * 3 + 0], w1 = W2[c * 3 + 1], w2 = W2[c * 3 + 2];
        float bc = b2[c];
#pragma unroll
        for (int r = 0; r < 16; r++) {
            float v = bc + ls[r * 3 + 0] * w0 + ls[r * 3 + 1] * w1 + ls[r * 3 + 2] * w2;
            hA[(128 + c) * HA_STRIDE + r] = fmaxf(v, 0.0f);
        }
    }
    __syncthreads();   // pool reads done + hA complete -> safe to alias pool

    // ---- phase 2 staging: Wct tile 0 (16 x 256 = 1024 float4) ----
#pragma unroll
    for (int j = 0; j < 8; j++) {
        int idx = tid + j * 128;
        int kk = idx >> 6, cq = (idx & 63) * 4;
        *(float4*)&wctBs[kk * 256 + cq] = *(const float4*)&g_Wct[kk * 256 + cq];
    }

    int c2 = cg * 4;                          // phase-2 col quad (0..252)
    ull acc2[4][4];
#pragma unroll
    for (int p = 0; p < 4; p++)
#pragma unroll
        for (int c = 0; c < 4; c++) acc2[p][c] = dup2(g_b34[c2 + c]);

    // ---- phase 2 mainloop: 16 K-tiles of 16 ----
    for (int kt = 0; kt < 16; kt++) {
        __syncthreads();
        float4 pw[8];
        if (kt + 1 < 16) {
            int kb = (kt + 1) * 16;
#pragma unroll
            for (int j = 0; j < 8; j++) {
                int idx = tid + j * 128;
                int kk = idx >> 6, cq = (idx & 63) * 4;
                pw[j] = *(const float4*)&g_Wct[(kb + kk) * 256 + cq];
            }
        }
        const float* Bc = wctBs + (kt & 1) * 4096;
        int k0 = kt * 16;
#pragma unroll
        for (int kk = 0; kk < 16; kk++) {
            int k = k0 + kk;
            F4U2 a0, a1;
            a0.f4 = *(const float4*)&hA[k * HA_STRIDE + rbase];
            a1.f4 = *(const float4*)&hA[k * HA_STRIDE + rbase + 4];
            F4U2 w; w.f4 = *(const float4*)&Bc[kk * 256 + c2];
#pragma unroll
            for (int c = 0; c < 4; c++) {
                ull d = dup2(w.f[c]);
                ffma2(acc2[0][c], a0.u2[0], d);
                ffma2(acc2[1][c], a0.u2[1], d);
                ffma2(acc2[2][c], a1.u2[0], d);
                ffma2(acc2[3][c], a1.u2[1], d);
            }
        }
        if (kt + 1 < 16) {
            float* dst = wctBs + ((kt + 1) & 1) * 4096;
#pragma unroll
            for (int j = 0; j < 8; j++) {
                int idx = tid + j * 128;
                int kk = idx >> 6, cq = (idx & 63) * 4;
                *(float4*)&dst[kk * 256 + cq] = pw[j];
            }
        }
    }

    // ---- phase 2 epilogue: coalesced direct stores ----
#pragma unroll
    for (int p = 0; p < 4; p++) {
        float2 vc[4];
#pragma unroll
        for (int c = 0; c < 4; c++) vc[c] = unpack2(acc2[p][c]);
        float4 o0, o1;
        o0.x = fmaxf(vc[0].x, 0.f); o0.y = fmaxf(vc[1].x, 0.f);
        o0.z = fmaxf(vc[2].x, 0.f); o0.w = fmaxf(vc[3].x, 0.f);
        o1.x = fmaxf(vc[0].y, 0.f); o1.y = fmaxf(vc[1].y, 0.f);
        o1.z = fmaxf(vc[2].y, 0.f); o1.w = fmaxf(vc[3].y, 0.f);
        size_t r0 = (size_t)(row0 + rbase + 2 * p) * 256 + c2;
        *(float4*)&out[r0]       = o0;
        *(float4*)&out[r0 + 256] = o1;
    }
}

// ------------------------------ launch --------------------------------------
extern "C" void kernel_launch(void* const* d_in, const int* in_sizes, int n_in,
                              void* d_out, int out_size) {
    const float* x  = (const float*)d_in[0];
    const float* lt = (const float*)d_in[1];
    const float* W1 = (const float*)d_in[2];
    const float* b1 = (const float*)d_in[3];
    const float* W2 = (const float*)d_in[4];
    const float* b2 = (const float*)d_in[5];
    const float* W3 = (const float*)d_in[6];
    const float* b3 = (const float*)d_in[7];
    const float* W4 = (const float*)d_in[8];
    const float* b4 = (const float*)d_in[9];
    float* out = (float*)d_out;

    int B = in_sizes[0] / (3 * P_PTS);
    if (B > MAXB) B = MAXB;

    static bool attr_set = false;
    if (!attr_set) {
        cudaFuncSetAttribute(mlp_kernel,
                             cudaFuncAttributeMaxDynamicSharedMemorySize,
                             SMEM_FLOATS * sizeof(float));
        attr_set = true;
    }

    foveate_kernel<<<B, 512>>>(x, lt, W1, W3, W4, b3, b4);
    mlp_kernel<<<B / 16, 128, SMEM_FLOATS * sizeof(float)>>>(lt, b1, W2, b2, out);
}